// round 3
// baseline (speedup 1.0000x reference)
#include <cuda_runtime.h>

#define DNUM 20
#define ONUM 19
#define MNUM 32
#define MM   (MNUM * MNUM)
#define NROWS (ONUM * ONUM * ONUM)        // 6859 (a,b,c) rows
#define NP3   (NROWS * DNUM)              // 137180 points in H3/X3
#define WPB 4
#define THREADS (WPB * 32)

// C[k][i][j] = cos(2*pi*k / (32*i + j + 2)), k in [0,19)
__device__ __align__(16) float g_C[ONUM * MM];
// scratch: 3-axis window sums (keep k), then M-transformed
__device__ __align__(16) float g_H3[NP3 * MNUM];
__device__ __align__(16) float g_X3[NP3 * MNUM];

__global__ void init_tabs() {
    int t = blockIdx.x * blockDim.x + threadIdx.x;
    if (t < ONUM * MM) {
        int k = t / MM;
        int r = t % MM;                  // r = i*32 + j, period = r + 2
        g_C[t] = cosf(6.283185307179586f * (float)k / (float)(r + 2));
    }
}

// H3[a,b,c,d',k] = sum over {da,db,dc} of h[a+da, b+db, c+dc, d', k]
__global__ __launch_bounds__(320) void k1_h3(const float* __restrict__ h) {
    const int abc = blockIdx.x;                  // 6859
    const int c = abc % ONUM;
    const int t = abc / ONUM;
    const int b = t % ONUM, a = t / ONUM;
    const float* base = h + ((a * DNUM + b) * DNUM + c) * (DNUM * MNUM);
    float* o = g_H3 + abc * (DNUM * MNUM);
#pragma unroll
    for (int e = threadIdx.x; e < DNUM * MNUM; e += 320) {
        const float* q = base + e;
        o[e] = ((__ldg(q)          + __ldg(q + 640))
             +  (__ldg(q + 12800)  + __ldg(q + 13440)))
             + ((__ldg(q + 256000) + __ldg(q + 256640))
             +  (__ldg(q + 268800) + __ldg(q + 269440)));
    }
}

// X3[p,j] = sum_k M_w[j,k] * H3[p,k]
#define K2_PTS 8
__global__ __launch_bounds__(256) void k2_matvec(const float* __restrict__ Mw) {
    const int lane = threadIdx.x & 31;
    float Mr[MNUM];
    {
        const float4* M4 = (const float4*)Mw + lane * 8;
#pragma unroll
        for (int v = 0; v < 8; ++v) {
            float4 m = __ldg(M4 + v);
            Mr[4*v+0] = m.x; Mr[4*v+1] = m.y; Mr[4*v+2] = m.z; Mr[4*v+3] = m.w;
        }
    }
    const int wid = blockIdx.x * 8 + (threadIdx.x >> 5);
    const int p0 = wid * K2_PTS;
#pragma unroll
    for (int tpt = 0; tpt < K2_PTS; ++tpt) {
        const int p = p0 + tpt;
        if (p < NP3) {
            const float4* H4 = (const float4*)(g_H3 + p * MNUM);
            float a0 = 0.f, a1 = 0.f, a2 = 0.f, a3 = 0.f;
#pragma unroll
            for (int v = 0; v < 8; ++v) {
                float4 hv = __ldg(H4 + v);       // uniform across lanes
                a0 = fmaf(Mr[4*v+0], hv.x, a0);
                a1 = fmaf(Mr[4*v+1], hv.y, a1);
                a2 = fmaf(Mr[4*v+2], hv.z, a2);
                a3 = fmaf(Mr[4*v+3], hv.w, a3);
            }
            g_X3[p * MNUM + lane] = (a0 + a1) + (a2 + a3);
        }
    }
}

// One window step. CUR = t_d state, OTH = t_{d+1}; ADV advances recurrence + prefetch.
#define BODY(CUR, OTH, ADV) {                                                  \
    float x = (cs0 + cs1) * 0.0625f;                                           \
    if (ADV) { cs0 = cs1; cs1 = __ldg(xp); xp += MNUM; }                       \
    float a0 = 0.f, a1 = 0.f, a2 = 0.f, a3 = 0.f;                              \
    _Pragma("unroll")                                                          \
    for (int j = 0; j < MNUM; j += 4) {                                        \
        float xb0 = __shfl_sync(0xffffffffu, x, j);                            \
        float xb1 = __shfl_sync(0xffffffffu, x, j + 1);                        \
        float xb2 = __shfl_sync(0xffffffffu, x, j + 2);                        \
        float xb3 = __shfl_sync(0xffffffffu, x, j + 3);                        \
        a0 = fmaf(xb0, CUR[j],     a0);                                        \
        a1 = fmaf(xb1, CUR[j + 1], a1);                                        \
        a2 = fmaf(xb2, CUR[j + 2], a2);                                        \
        a3 = fmaf(xb3, CUR[j + 3], a3);                                        \
        if (ADV) {                                                             \
            CUR[j]     = fmaf(tc1[j],     OTH[j],     -CUR[j]);                \
            CUR[j + 1] = fmaf(tc1[j + 1], OTH[j + 1], -CUR[j + 1]);            \
            CUR[j + 2] = fmaf(tc1[j + 2], OTH[j + 2], -CUR[j + 2]);            \
            CUR[j + 3] = fmaf(tc1[j + 3], OTH[j + 3], -CUR[j + 3]);            \
        }                                                                      \
    }                                                                          \
    *op = (a0 + a1) + (a2 + a3); op += MNUM;                                   \
}

__global__ __launch_bounds__(THREADS)
void sdd_main(const float* __restrict__ P, float* __restrict__ out) {
    const int w = threadIdx.x >> 5, lane = threadIdx.x & 31;
    const int row = blockIdx.x * WPB + w;
    if (row >= NROWS) return;

    const int a = row / (ONUM * ONUM);
    const int bc = row - a * (ONUM * ONUM);
    const int b = bc / ONUM;
    const int c = bc - b * ONUM;

    // Per-lane (lane = i): tc1 = 2*cos(theta_i,:), u = t_0 = P.*Ca.*Cb.*Cc, v = t_1
    float tc1[MNUM], u[MNUM], v[MNUM];
    {
        const float4* T4 = (const float4*)(g_C + MM) + lane * 8;   // k=1 slab
        const float4* P4 = (const float4*)P + lane * 8;
        const float4* A4 = (const float4*)g_C + a * (MM / 4) + lane * 8;
        const float4* B4 = (const float4*)g_C + b * (MM / 4) + lane * 8;
        const float4* C4 = (const float4*)g_C + c * (MM / 4) + lane * 8;
#pragma unroll
        for (int v4 = 0; v4 < 8; ++v4) {
            float4 tv = __ldg(T4 + v4);
            float4 pv = __ldg(P4 + v4), av = __ldg(A4 + v4);
            float4 bv = __ldg(B4 + v4), cv = __ldg(C4 + v4);
            float t0 = tv.x, t1 = tv.y, t2 = tv.z, t3 = tv.w;
            tc1[4*v4+0] = 2.0f * t0; tc1[4*v4+1] = 2.0f * t1;
            tc1[4*v4+2] = 2.0f * t2; tc1[4*v4+3] = 2.0f * t3;
            u[4*v4+0] = pv.x * av.x * bv.x * cv.x;
            u[4*v4+1] = pv.y * av.y * bv.y * cv.y;
            u[4*v4+2] = pv.z * av.z * bv.z * cv.z;
            u[4*v4+3] = pv.w * av.w * bv.w * cv.w;
            v[4*v4+0] = u[4*v4+0] * t0;
            v[4*v4+1] = u[4*v4+1] * t1;
            v[4*v4+2] = u[4*v4+2] * t2;
            v[4*v4+3] = u[4*v4+3] * t3;
        }
    }

    // x chain over d': x(d) = (X3[d] + X3[d+1]) / 16, lane = j here
    const float* xp = g_X3 + row * (DNUM * MNUM) + lane;
    float cs0 = __ldg(xp);
    float cs1 = __ldg(xp + MNUM);
    xp += 2 * MNUM;
    float* op = out + row * (ONUM * MNUM) + lane;

#pragma unroll 1
    for (int it = 0; it < 9; ++it) {
        BODY(u, v, 1);
        BODY(v, u, 1);
    }
    BODY(u, v, 0);
}

extern "C" void kernel_launch(void* const* d_in, const int* in_sizes, int n_in,
                              void* d_out, int out_size) {
    const float* h  = (const float*)d_in[0];   // hypervol [20,20,20,20,32]
    const float* Mw = (const float*)d_in[1];   // M_w [32,32]
    const float* P  = (const float*)d_in[2];   // P  [32,32]
    float* out = (float*)d_out;                // [130321, 32]

    init_tabs<<<(ONUM * MM + 511) / 512, 512>>>();
    k1_h3<<<NROWS, 320>>>(h);
    k2_matvec<<<(NP3 + 8 * K2_PTS - 1) / (8 * K2_PTS), 256>>>(Mw);
    sdd_main<<<(NROWS + WPB - 1) / WPB, THREADS>>>(P, out);
}